// round 3
// baseline (speedup 1.0000x reference)
#include <cuda_runtime.h>
#include <math.h>

// ---------------- problem constants ----------------
#define NWIN 256
#define NTOK 256
#define NC   384
#define NH   12
#define DH   32
#define MROWS (NWIN*NTOK)
#define BHD (NTOK*DH)

typedef unsigned long long u64;

// ---------------- packed f32x2 helpers -------------
__device__ __forceinline__ u64 pk2(float x, float y){ u64 d; asm("mov.b64 %0,{%1,%2};":"=l"(d):"f"(x),"f"(y)); return d; }
__device__ __forceinline__ u64 dup2(float x){ u64 d; asm("mov.b64 %0,{%1,%1};":"=l"(d):"f"(x)); return d; }
__device__ __forceinline__ float2 up2(u64 d){ float2 r; asm("mov.b64 {%0,%1},%2;":"=f"(r.x),"=f"(r.y):"l"(d)); return r; }
__device__ __forceinline__ void fma2(u64& d, u64 a, u64 b){ asm("fma.rn.f32x2 %0,%1,%2,%0;":"+l"(d):"l"(a),"l"(b)); }

union F4U { float4 f; u64 u[2]; };

// ---------------- scratch ----------------
__device__ float g_q[(size_t)NWIN*NH*BHD];
__device__ float g_k[(size_t)NWIN*NH*BHD];
__device__ float g_v[(size_t)NWIN*NH*BHD];
__device__ float g_ao[(size_t)MROWS*NC];
__device__ float g_bt[961*NH];
__device__ float g_rpbT[(size_t)NH*NTOK*NTOK];   // [h][j][qi]

// ================= CPB MLP ==============
__global__ void cpb_kernel(const float* __restrict__ table,
                           const float* __restrict__ w1,
                           const float* __restrict__ b1,
                           const float* __restrict__ w2)
{
    __shared__ float sh[512];
    const int e = blockIdx.x;
    const int t = threadIdx.x;
    const float c0 = table[e*2+0], c1 = table[e*2+1];
    float hid = fmaf(c0, w1[t*2+0], fmaf(c1, w1[t*2+1], b1[t]));
    sh[t] = fmaxf(hid, 0.f);
    __syncthreads();
    const int w = t >> 5, l = t & 31;
    if (w < NH) {
        float s = 0.f;
        #pragma unroll
        for (int i = 0; i < 16; i++)
            s = fmaf(sh[l + i*32], w2[w*512 + l + i*32], s);
        #pragma unroll
        for (int o = 16; o > 0; o >>= 1)
            s += __shfl_xor_sync(0xffffffffu, s, o);
        if (l == 0) g_bt[e*NH + w] = s;
    }
}

// ============ gather + 16*sigmoid -> [h][j][qi] =====
__global__ void gather_kernel(const int* __restrict__ rpi)
{
    const int qi = threadIdx.x;
    const int j  = blockIdx.x;
    const int idx = rpi[qi*NTOK + j];
    #pragma unroll
    for (int h = 0; h < NH; h++) {
        float bv = g_bt[idx*NH + h];
        float sg = 16.f / (1.f + __expf(-bv));
        g_rpbT[((size_t)h*NTOK + j)*NTOK + qi] = sg;
    }
}

// ====================== GEMM core (f32x2, A pre-duplicated in smem) =====
// As2[kk][2r]==As2[kk][2r+1]==A[row0+r][k0+kk]; inner loop: 4 broadcast
// LDS.128 give 8 dup'd a-pairs, 2 LDS.128 give 4 packed b-col-pairs.
#define AS2_STRIDE 260
#define BS_STRIDE  132
#define GEMM_SMEM ((32*AS2_STRIDE + 32*BS_STRIDE)*4)

__device__ __forceinline__ void gemm_tile_f32x2(
    const float* __restrict__ A, const float* __restrict__ W,
    int row0, int col0, int t, float* As2, float* Bs, u64 acc[8][4])
{
    const int tx = t & 15, ty = t >> 4;
    #pragma unroll
    for (int i = 0; i < 8; i++)
        #pragma unroll
        for (int j = 0; j < 4; j++) acc[i][j] = 0ull;

    for (int k0 = 0; k0 < NC; k0 += 32) {
        #pragma unroll
        for (int i = 0; i < 4; i++) {
            int f = t + i*256;
            int r = f >> 3, kq = (f & 7) << 2;
            float4 va = *(const float4*)(A + (size_t)(row0 + r)*NC + k0 + kq);
            float vv[4] = {va.x, va.y, va.z, va.w};
            #pragma unroll
            for (int ii = 0; ii < 4; ii++) {
                int sel = (ii + (kq >> 2)) & 3;        // perm: cut STS conflicts
                float x = vv[sel];
                *(float2*)(As2 + (kq + sel)*AS2_STRIDE + 2*r) = make_float2(x, x);
            }
            float4 wb = *(const float4*)(W + (size_t)(col0 + r)*NC + k0 + kq);
            Bs[(kq+0)*BS_STRIDE + r] = wb.x;
            Bs[(kq+1)*BS_STRIDE + r] = wb.y;
            Bs[(kq+2)*BS_STRIDE + r] = wb.z;
            Bs[(kq+3)*BS_STRIDE + r] = wb.w;
        }
        __syncthreads();
        #pragma unroll 8
        for (int kk = 0; kk < 32; kk++) {
            const float* ap = As2 + kk*AS2_STRIDE + 8*ty;
            F4U a01, a23, a45, a67;
            a01.f = *(const float4*)(ap);
            a23.f = *(const float4*)(ap + 4);
            a45.f = *(const float4*)(ap + 128);
            a67.f = *(const float4*)(ap + 132);
            const float* bp = Bs + kk*BS_STRIDE + tx*4;
            F4U b0, b1;
            b0.f = *(const float4*)(bp);
            b1.f = *(const float4*)(bp + 64);
            u64 a2[8] = {a01.u[0],a01.u[1],a23.u[0],a23.u[1],
                         a45.u[0],a45.u[1],a67.u[0],a67.u[1]};
            u64 b2[4] = {b0.u[0], b0.u[1], b1.u[0], b1.u[1]};
            #pragma unroll
            for (int i = 0; i < 8; i++)
                #pragma unroll
                for (int jp = 0; jp < 4; jp++)
                    fma2(acc[i][jp], a2[i], b2[jp]);
        }
        __syncthreads();
    }
}

// ================= QKV GEMM ===========
__global__ __launch_bounds__(256, 2) void qkv_gemm_kernel(
    const float* __restrict__ A,
    const float* __restrict__ W,
    const float* __restrict__ qb,
    const float* __restrict__ vb)
{
    extern __shared__ float smg[];
    float* As2 = smg;
    float* Bs  = smg + 32*AS2_STRIDE;
    const int row0 = blockIdx.y * 128;
    const int col0 = blockIdx.x * 128;
    const int t = threadIdx.x;
    const int tx = t & 15, ty = t >> 4;

    u64 acc[8][4];
    gemm_tile_f32x2(A, W, row0, col0, t, As2, Bs, acc);

    #pragma unroll
    for (int g = 0; g < 2; g++) {
        const int cglob = col0 + g*64 + tx*4;
        const int which = cglob / NC;
        const int cw = cglob % NC;
        const int hh = cw >> 5;
        const int d0 = cw & 31;
        float bias[4];
        #pragma unroll
        for (int j = 0; j < 4; j++)
            bias[j] = (which == 0) ? qb[cw+j] : (which == 2) ? vb[cw+j] : 0.f;
        float* dst = (which == 0) ? g_q : (which == 1) ? g_k : g_v;
        #pragma unroll
        for (int i = 0; i < 8; i++) {
            int r = row0 + (i>>2)*64 + ty*4 + (i&3);
            int b = r >> 8, n = r & 255;
            float2 p0 = up2(acc[i][g*2+0]);
            float2 p1 = up2(acc[i][g*2+1]);
            float* p = dst + ((((size_t)b*NH + hh)*NTOK) + n)*DH + d0;
            *(float4*)p = make_float4(p0.x+bias[0], p0.y+bias[1], p1.x+bias[2], p1.y+bias[3]);
        }
    }
}

// ================= Proj GEMM =======
__global__ __launch_bounds__(256, 2) void proj_gemm_kernel(
    const float* __restrict__ W,
    const float* __restrict__ pb,
    float* __restrict__ out)
{
    extern __shared__ float smg[];
    float* As2 = smg;
    float* Bs  = smg + 32*AS2_STRIDE;
    const int row0 = blockIdx.y * 128;
    const int col0 = blockIdx.x * 128;
    const int t = threadIdx.x;
    const int tx = t & 15, ty = t >> 4;

    u64 acc[8][4];
    gemm_tile_f32x2(g_ao, W, row0, col0, t, As2, Bs, acc);

    #pragma unroll
    for (int g = 0; g < 2; g++) {
        const int cglob = col0 + g*64 + tx*4;
        float bias[4];
        #pragma unroll
        for (int j = 0; j < 4; j++) bias[j] = pb[cglob + j];
        #pragma unroll
        for (int i = 0; i < 8; i++) {
            int r = row0 + (i>>2)*64 + ty*4 + (i&3);
            float2 p0 = up2(acc[i][g*2+0]);
            float2 p1 = up2(acc[i][g*2+1]);
            float* p = out + (size_t)r*NC + cglob;
            *(float4*)p = make_float4(p0.x+bias[0], p0.y+bias[1], p1.x+bias[2], p1.y+bias[3]);
        }
    }
}

// ================= Attention: 128 threads, 2 queries/thread ==============
// Single-pass softmax with static shift M = sc + 16 (scores provably <= M).
__global__ __launch_bounds__(128, 2) void attn_kernel(const float* __restrict__ logit_scale)
{
    extern __shared__ float sm[];
    float* Ks = sm;          // 8192 floats (L2-normalized in place)
    float* Vs = sm + BHD;

    const int bh = blockIdx.x;
    const int h  = bh % NH;
    const int b  = bh / NH;
    const int t  = threadIdx.x;   // 0..127 -> queries 2t, 2t+1

    const float* Kg = g_k + (size_t)bh*BHD;
    const float* Vg = g_v + (size_t)bh*BHD;
    #pragma unroll
    for (int i = t; i < BHD/4; i += 128) {
        ((float4*)Ks)[i] = ((const float4*)Kg)[i];
        ((float4*)Vs)[i] = ((const float4*)Vg)[i];
    }
    __syncthreads();

    // normalize K rows in place (transposed warp access: conflict-free)
    {
        const int w = t >> 5, l = t & 31;
        #pragma unroll 4
        for (int rr = 0; rr < 64; rr++) {
            int r = (w << 6) + rr;
            float x = Ks[r*DH + l];
            float s = x * x;
            #pragma unroll
            for (int o = 16; o > 0; o >>= 1)
                s += __shfl_xor_sync(0xffffffffu, s, o);
            float inv = 1.f / fmaxf(sqrtf(s), 1e-12f);
            Ks[r*DH + l] = x * inv;
        }
    }

    const float sc = __expf(fminf(logit_scale[h], 4.6051702f));
    const float M  = sc + 16.f;

    // two query rows: normalize + scale, pack to f32x2
    u64 q2a[16], q2b[16];
    {
        const float* Qg = g_q + (size_t)bh*BHD + (2*t)*DH;
        float qa[DH], qb_[DH];
        float sa = 0.f, sb = 0.f;
        #pragma unroll
        for (int d = 0; d < DH; d += 4) {
            float4 v4 = *(const float4*)(Qg + d);
            qa[d]=v4.x; qa[d+1]=v4.y; qa[d+2]=v4.z; qa[d+3]=v4.w;
            float4 w4 = *(const float4*)(Qg + DH + d);
            qb_[d]=w4.x; qb_[d+1]=w4.y; qb_[d+2]=w4.z; qb_[d+3]=w4.w;
        }
        #pragma unroll
        for (int d = 0; d < DH; d++) { sa = fmaf(qa[d],qa[d],sa); sb = fmaf(qb_[d],qb_[d],sb); }
        float fa = sc / fmaxf(sqrtf(sa), 1e-12f);
        float fb = sc / fmaxf(sqrtf(sb), 1e-12f);
        #pragma unroll
        for (int i = 0; i < 16; i++) {
            q2a[i] = pk2(qa[2*i]*fa, qa[2*i+1]*fa);
            q2b[i] = pk2(qb_[2*i]*fb, qb_[2*i+1]*fb);
        }
    }
    __syncthreads();

    const float* rp = g_rpbT + (size_t)h*(NTOK*NTOK) + 2*t;

    float la = 0.f, lb = 0.f;
    u64 acca[16], accb[16];
    #pragma unroll
    for (int i = 0; i < 16; i++) { acca[i] = 0ull; accb[i] = 0ull; }

    #pragma unroll 2
    for (int j = 0; j < NTOK; j++) {
        F4U kr[8];
        const float4* kp = (const float4*)(Ks + j*DH);
        #pragma unroll
        for (int i = 0; i < 8; i++) kr[i].f = kp[i];

        u64 s0a=0ull, s1a=0ull, s0b=0ull, s1b=0ull;
        #pragma unroll
        for (int i = 0; i < 8; i++) {
            fma2(s0a, q2a[2*i+0], kr[i].u[0]);
            fma2(s1a, q2a[2*i+1], kr[i].u[1]);
            fma2(s0b, q2b[2*i+0], kr[i].u[0]);
            fma2(s1b, q2b[2*i+1], kr[i].u[1]);
        }
        float2 bias = *(const float2*)(rp + j*NTOK);
        float2 ua0 = up2(s0a), ua1 = up2(s1a);
        float2 ub0 = up2(s0b), ub1 = up2(s1b);
        float sa = (ua0.x + ua0.y) + (ua1.x + ua1.y);
        float sb = (ub0.x + ub0.y) + (ub1.x + ub1.y);
        float pa = __expf(sa + bias.x - M);
        float pb = __expf(sb + bias.y - M);
        la += pa; lb += pb;

        u64 p2a = dup2(pa), p2b = dup2(pb);
        F4U vr[8];
        const float4* vp = (const float4*)(Vs + j*DH);
        #pragma unroll
        for (int i = 0; i < 8; i++) vr[i].f = vp[i];
        #pragma unroll
        for (int i = 0; i < 8; i++) {
            fma2(acca[2*i+0], p2a, vr[i].u[0]);
            fma2(acca[2*i+1], p2a, vr[i].u[1]);
            fma2(accb[2*i+0], p2b, vr[i].u[0]);
            fma2(accb[2*i+1], p2b, vr[i].u[1]);
        }
    }

    const float inva = 1.f / la;
    const float invb = 1.f / lb;
    float* oa = g_ao + (size_t)(b*NTOK + 2*t)*NC + h*DH;
    float* ob = oa + NC;
    #pragma unroll
    for (int i = 0; i < 16; i += 2) {
        float2 x = up2(acca[i]), y = up2(acca[i+1]);
        *(float4*)(oa + i*2) = make_float4(x.x*inva, x.y*inva, y.x*inva, y.y*inva);
        float2 u = up2(accb[i]), v = up2(accb[i+1]);
        *(float4*)(ob + i*2) = make_float4(u.x*invb, u.y*invb, v.x*invb, v.y*invb);
    }
}

// =========================== launcher ====================================
extern "C" void kernel_launch(void* const* d_in, const int* in_sizes, int n_in,
                              void* d_out, int out_size)
{
    const float* x      = (const float*)d_in[0];
    const float* qkv_w  = (const float*)d_in[1];
    const float* q_bias = (const float*)d_in[2];
    const float* v_bias = (const float*)d_in[3];
    const float* lscale = (const float*)d_in[4];
    const float* cpb_w1 = (const float*)d_in[5];
    const float* cpb_b1 = (const float*)d_in[6];
    const float* cpb_w2 = (const float*)d_in[7];
    const float* proj_w = (const float*)d_in[8];
    const float* proj_b = (const float*)d_in[9];
    const float* rtab   = (const float*)d_in[10];
    const int*   rpi    = (const int*)d_in[11];
    float* out = (float*)d_out;

    const int attn_smem = 2*BHD*(int)sizeof(float); // 65536 B
    cudaFuncSetAttribute(attn_kernel, cudaFuncAttributeMaxDynamicSharedMemorySize, attn_smem);
    cudaFuncSetAttribute(qkv_gemm_kernel, cudaFuncAttributeMaxDynamicSharedMemorySize, GEMM_SMEM);
    cudaFuncSetAttribute(proj_gemm_kernel, cudaFuncAttributeMaxDynamicSharedMemorySize, GEMM_SMEM);

    cpb_kernel<<<961, 512>>>(rtab, cpb_w1, cpb_b1, cpb_w2);
    gather_kernel<<<NTOK, NTOK>>>(rpi);

    dim3 gq(1152/128, MROWS/128);
    qkv_gemm_kernel<<<gq, 256, GEMM_SMEM>>>(x, qkv_w, q_bias, v_bias);

    attn_kernel<<<NWIN*NH, 128, attn_smem>>>(lscale);

    dim3 gp(NC/128, MROWS/128);
    proj_gemm_kernel<<<gp, 256, GEMM_SMEM>>>(proj_w, proj_b, out);
}

// round 7
// speedup vs baseline: 1.3312x; 1.3312x over previous
#include <cuda_runtime.h>
#include <cuda_bf16.h>
#include <math.h>

// ---------------- problem constants ----------------
#define NWIN 256
#define NTOK 256
#define NC   384
#define NH   12
#define DH   32
#define MROWS (NWIN*NTOK)
#define BHD (NTOK*DH)

typedef unsigned long long u64;
typedef unsigned int u32;

// ---------------- packed f32x2 helpers -------------
__device__ __forceinline__ u64 pk2(float x, float y){ u64 d; asm("mov.b64 %0,{%1,%2};":"=l"(d):"f"(x),"f"(y)); return d; }
__device__ __forceinline__ u64 dup2(float x){ u64 d; asm("mov.b64 %0,{%1,%1};":"=l"(d):"f"(x)); return d; }
__device__ __forceinline__ float2 up2(u64 d){ float2 r; asm("mov.b64 {%0,%1},%2;":"=f"(r.x),"=f"(r.y):"l"(d)); return r; }
__device__ __forceinline__ void fma2(u64& d, u64 a, u64 b){ asm("fma.rn.f32x2 %0,%1,%2,%0;":"+l"(d):"l"(a),"l"(b)); }

// ---------------- mma helper (baseline PTX, sm_80+) ------
__device__ __forceinline__ void mma16816(float c[4], const u32 a[4], u32 b0, u32 b1) {
    asm volatile(
        "mma.sync.aligned.m16n8k16.row.col.f32.bf16.bf16.f32 "
        "{%0,%1,%2,%3},{%4,%5,%6,%7},{%8,%9},{%0,%1,%2,%3};"
        : "+f"(c[0]), "+f"(c[1]), "+f"(c[2]), "+f"(c[3])
        : "r"(a[0]), "r"(a[1]), "r"(a[2]), "r"(a[3]), "r"(b0), "r"(b1));
}

// ---------------- scratch (referenced ONLY from device code) ----------
__device__ float g_q[(size_t)NWIN*NH*BHD];
__device__ float g_k[(size_t)NWIN*NH*BHD];
__device__ float g_v[(size_t)NWIN*NH*BHD];
__device__ float g_bt[961*NH];
__device__ float g_rpbT[(size_t)NH*NTOK*NTOK];   // [h][j][qi]
// bf16 split buffers
__device__ __align__(16) __nv_bfloat16 g_xh[(size_t)MROWS*NC];
__device__ __align__(16) __nv_bfloat16 g_xl[(size_t)MROWS*NC];
__device__ __align__(16) __nv_bfloat16 g_qwh[1152*NC];
__device__ __align__(16) __nv_bfloat16 g_qwl[1152*NC];
__device__ __align__(16) __nv_bfloat16 g_pwh[NC*NC];
__device__ __align__(16) __nv_bfloat16 g_pwl[NC*NC];
__device__ __align__(16) __nv_bfloat16 g_aoh[(size_t)MROWS*NC];
__device__ __align__(16) __nv_bfloat16 g_aol[(size_t)MROWS*NC];

// ================= split fp32 -> bf16 hi + lo ==============
// Destination selected IN DEVICE CODE (passing __device__ globals as kernel
// args from host silently passes the host shadow address -> ATS blackhole).
__global__ void split_kernel(const float* __restrict__ src, int n4, int which)
{
    __nv_bfloat16* hi = (which == 0) ? g_xh : (which == 1) ? g_qwh : g_pwh;
    __nv_bfloat16* lo = (which == 0) ? g_xl : (which == 1) ? g_qwl : g_pwl;
    int i = blockIdx.x*blockDim.x + threadIdx.x;
    if (i >= n4) return;
    float4 v = ((const float4*)src)[i];
    float vals[4] = {v.x, v.y, v.z, v.w};
    __nv_bfloat16 h[4], l[4];
    #pragma unroll
    for (int j = 0; j < 4; j++) {
        h[j] = __float2bfloat16(vals[j]);
        l[j] = __float2bfloat16(vals[j] - __bfloat162float(h[j]));
    }
    ((__nv_bfloat162*)hi)[2*i+0] = __nv_bfloat162(h[0], h[1]);
    ((__nv_bfloat162*)hi)[2*i+1] = __nv_bfloat162(h[2], h[3]);
    ((__nv_bfloat162*)lo)[2*i+0] = __nv_bfloat162(l[0], l[1]);
    ((__nv_bfloat162*)lo)[2*i+1] = __nv_bfloat162(l[2], l[3]);
}

// ================= CPB MLP ==============
__global__ void cpb_kernel(const float* __restrict__ table,
                           const float* __restrict__ w1,
                           const float* __restrict__ b1,
                           const float* __restrict__ w2)
{
    __shared__ float sh[512];
    const int e = blockIdx.x;
    const int t = threadIdx.x;
    const float c0 = table[e*2+0], c1 = table[e*2+1];
    float hid = fmaf(c0, w1[t*2+0], fmaf(c1, w1[t*2+1], b1[t]));
    sh[t] = fmaxf(hid, 0.f);
    __syncthreads();
    const int w = t >> 5, l = t & 31;
    if (w < NH) {
        float s = 0.f;
        #pragma unroll
        for (int i = 0; i < 16; i++)
            s = fmaf(sh[l + i*32], w2[w*512 + l + i*32], s);
        #pragma unroll
        for (int o = 16; o > 0; o >>= 1)
            s += __shfl_xor_sync(0xffffffffu, s, o);
        if (l == 0) g_bt[e*NH + w] = s;
    }
}

__global__ void gather_kernel(const int* __restrict__ rpi)
{
    const int qi = threadIdx.x;
    const int j  = blockIdx.x;
    const int idx = rpi[qi*NTOK + j];
    #pragma unroll
    for (int h = 0; h < NH; h++) {
        float bv = g_bt[idx*NH + h];
        float sg = 16.f / (1.f + __expf(-bv));
        g_rpbT[((size_t)h*NTOK + j)*NTOK + qi] = sg;
    }
}

// ====================== HMMA bf16x3 GEMM mainloop (conservative) ========
// C[128,128] = A_split @ B_split^T, 18 k-tiles (3 segs x 6 of BK=64):
// Ah*Bh + Ah*Bl + Al*Bh. No cp.async, no swizzle, no ldmatrix.
// smem: As/Bs [128 rows][64 bf16 + 8 pad] (stride 72 elems = 144 B).
#define AS_STR 72
#define HM_SMEM (2*128*AS_STR*2)   // 36864 bytes

__device__ __forceinline__ void hmma_mainloop(
    const __nv_bfloat16* __restrict__ Ah, const __nv_bfloat16* __restrict__ Al,
    const __nv_bfloat16* __restrict__ Bh, const __nv_bfloat16* __restrict__ Bl,
    int row0, int col0, __nv_bfloat16* As, __nv_bfloat16* Bs, float acc[4][4][4])
{
    const int t = threadIdx.x;
    const int r = t >> 1, hf = t & 1;          // row 0..127, k-half 0/1

    const __nv_bfloat16* aH = Ah + (size_t)(row0 + r)*NC + hf*32;
    const __nv_bfloat16* aL = Al + (size_t)(row0 + r)*NC + hf*32;
    const __nv_bfloat16* bH = Bh + (size_t)(col0 + r)*NC + hf*32;
    const __nv_bfloat16* bL = Bl + (size_t)(col0 + r)*NC + hf*32;

    uint4 ra[4], rb[4];
    auto gload = [&](int kt) {
        const int seg = kt / 6;
        const int kk  = (kt - seg*6) * 64;
        const uint4* ap = (const uint4*)(((seg == 2) ? aL : aH) + kk);
        const uint4* bp = (const uint4*)(((seg == 1) ? bL : bH) + kk);
        #pragma unroll
        for (int j = 0; j < 4; j++) { ra[j] = ap[j]; rb[j] = bp[j]; }
    };

    const int wid = t >> 5, lane = t & 31;
    const int wm = wid & 1, wn = wid >> 1;      // warp grid 2(m) x 4(n)
    const int gid = lane >> 2, tig = lane & 3;

    gload(0);

    #pragma unroll 1
    for (int kt = 0; kt < 18; kt++) {
        // stage regs -> smem
        __nv_bfloat16* as = As + r*AS_STR + hf*32;
        __nv_bfloat16* bs = Bs + r*AS_STR + hf*32;
        #pragma unroll
        for (int j = 0; j < 4; j++) {
            *(uint4*)(as + j*8) = ra[j];
            *(uint4*)(bs + j*8) = rb[j];
        }
        __syncthreads();
        if (kt < 17) gload(kt + 1);   // prefetch next tile into regs

        #pragma unroll
        for (int ks = 0; ks < 4; ks++) {
            const int k0 = ks*16 + tig*2;
            u32 a[4][4];
            #pragma unroll
            for (int mf = 0; mf < 4; mf++) {
                const int rb_ = wm*64 + mf*16 + gid;
                a[mf][0] = *(const u32*)&As[rb_*AS_STR + k0];
                a[mf][1] = *(const u32*)&As[(rb_+8)*AS_STR + k0];
                a[mf][2] = *(const u32*)&As[rb_*AS_STR + k0 + 8];
                a[mf][3] = *(const u32*)&As[(rb_+8)*AS_STR + k0 + 8];
            }
            u32 b[4][2];
            #pragma unroll
            for (int nf = 0; nf < 4; nf++) {
                const int nb = wn*32 + nf*8 + gid;
                b[nf][0] = *(const u32*)&Bs[nb*AS_STR + k0];
                b[nf][1] = *(const u32*)&Bs[nb*AS_STR + k0 + 8];
            }
            #pragma unroll
            for (int mf = 0; mf < 4; mf++)
                #pragma unroll
                for (int nf = 0; nf < 4; nf++)
                    mma16816(acc[mf][nf], a[mf], b[nf][0], b[nf][1]);
        }
        __syncthreads();
    }
}

// ================= QKV GEMM (HMMA) ===========
__global__ __launch_bounds__(256, 2) void qkv_hm_kernel(
    const float* __restrict__ qb, const float* __restrict__ vb)
{
    extern __shared__ __nv_bfloat16 smbf[];
    __nv_bfloat16* As = smbf;
    __nv_bfloat16* Bs = smbf + 128*AS_STR;
    const int row0 = blockIdx.y * 128;
    const int col0 = blockIdx.x * 128;

    float acc[4][4][4];
    #pragma unroll
    for (int i = 0; i < 4; i++)
        #pragma unroll
        for (int j = 0; j < 4; j++)
            #pragma unroll
            for (int k = 0; k < 4; k++) acc[i][j][k] = 0.f;

    hmma_mainloop(g_xh, g_xl, g_qwh, g_qwl, row0, col0, As, Bs, acc);

    const int t = threadIdx.x;
    const int wid = t >> 5, lane = t & 31;
    const int wm = wid & 1, wn = wid >> 1;
    const int r_in = lane >> 2, c_in = (lane & 3)*2;

    #pragma unroll
    for (int nf = 0; nf < 4; nf++) {
        const int cg = col0 + wn*32 + nf*8 + c_in;
        const int which = cg / NC;
        const int cw = cg % NC;
        const int hh = cw >> 5, d0 = cw & 31;
        const float b0 = (which == 0) ? qb[cw]   : (which == 2) ? vb[cw]   : 0.f;
        const float b1 = (which == 0) ? qb[cw+1] : (which == 2) ? vb[cw+1] : 0.f;
        float* base = (which == 0) ? g_q : (which == 1) ? g_k : g_v;
        #pragma unroll
        for (int mf = 0; mf < 4; mf++) {
            int m0 = row0 + wm*64 + mf*16 + r_in;
            int bb = m0 >> 8, nn = m0 & 255;
            float* p = base + ((((size_t)bb*NH + hh)*NTOK) + nn)*DH + d0;
            *(float2*)p = make_float2(acc[mf][nf][0] + b0, acc[mf][nf][1] + b1);
            int m1 = m0 + 8; bb = m1 >> 8; nn = m1 & 255;
            p = base + ((((size_t)bb*NH + hh)*NTOK) + nn)*DH + d0;
            *(float2*)p = make_float2(acc[mf][nf][2] + b0, acc[mf][nf][3] + b1);
        }
    }
}

// ================= Proj GEMM (HMMA) ===========
__global__ __launch_bounds__(256, 2) void proj_hm_kernel(
    const float* __restrict__ pb, float* __restrict__ out)
{
    extern __shared__ __nv_bfloat16 smbf[];
    __nv_bfloat16* As = smbf;
    __nv_bfloat16* Bs = smbf + 128*AS_STR;
    const int row0 = blockIdx.y * 128;
    const int col0 = blockIdx.x * 128;

    float acc[4][4][4];
    #pragma unroll
    for (int i = 0; i < 4; i++)
        #pragma unroll
        for (int j = 0; j < 4; j++)
            #pragma unroll
            for (int k = 0; k < 4; k++) acc[i][j][k] = 0.f;

    hmma_mainloop(g_aoh, g_aol, g_pwh, g_pwl, row0, col0, As, Bs, acc);

    const int t = threadIdx.x;
    const int wid = t >> 5, lane = t & 31;
    const int wm = wid & 1, wn = wid >> 1;
    const int r_in = lane >> 2, c_in = (lane & 3)*2;

    #pragma unroll
    for (int nf = 0; nf < 4; nf++) {
        const int cg = col0 + wn*32 + nf*8 + c_in;
        const float b0 = pb[cg], b1 = pb[cg+1];
        #pragma unroll
        for (int mf = 0; mf < 4; mf++) {
            int m0 = row0 + wm*64 + mf*16 + r_in;
            *(float2*)(out + (size_t)m0*NC + cg) =
                make_float2(acc[mf][nf][0] + b0, acc[mf][nf][1] + b1);
            *(float2*)(out + (size_t)(m0+8)*NC + cg) =
                make_float2(acc[mf][nf][2] + b0, acc[mf][nf][3] + b1);
        }
    }
}

// ================= Attention (R2 core; bf16 hi/lo epilogue) ========
__global__ __launch_bounds__(256, 2) void attn_kernel(const float* __restrict__ logit_scale)
{
    extern __shared__ float sm[];
    float* Ks = sm;
    float* Vs = sm + BHD;

    const int bh = blockIdx.x;
    const int h  = bh % NH;
    const int b  = bh / NH;
    const int t  = threadIdx.x;

    const float* Kg = g_k + (size_t)bh*BHD;
    const float* Vg = g_v + (size_t)bh*BHD;
    #pragma unroll
    for (int i = t; i < BHD/4; i += 256) {
        ((float4*)Ks)[i] = ((const float4*)Kg)[i];
        ((float4*)Vs)[i] = ((const float4*)Vg)[i];
    }
    __syncthreads();

    {
        const int w = t >> 5, l = t & 31;
        #pragma unroll 4
        for (int rr = 0; rr < 32; rr++) {
            int r = (w << 5) + rr;
            float x = Ks[r*DH + l];
            float s = x * x;
            #pragma unroll
            for (int o = 16; o > 0; o >>= 1)
                s += __shfl_xor_sync(0xffffffffu, s, o);
            float inv = 1.f / fmaxf(sqrtf(s), 1e-12f);
            Ks[r*DH + l] = x * inv;
        }
    }

    const float sc = __expf(fminf(logit_scale[h], 4.6051702f));
    const float M  = sc + 16.f;
    u64 q2[16];
    {
        const float* Qg = g_q + (size_t)bh*BHD + t*DH;
        float q[DH];
        float s = 0.f;
        #pragma unroll
        for (int d = 0; d < DH; d += 4) {
            float4 v4 = *(const float4*)(Qg + d);
            q[d] = v4.x; q[d+1] = v4.y; q[d+2] = v4.z; q[d+3] = v4.w;
        }
        #pragma unroll
        for (int d = 0; d < DH; d++) s = fmaf(q[d], q[d], s);
        float f = sc / fmaxf(sqrtf(s), 1e-12f);
        #pragma unroll
        for (int i = 0; i < 16; i++) q2[i] = pk2(q[2*i]*f, q[2*i+1]*f);
    }
    __syncthreads();

    const float* rp = g_rpbT + (size_t)h*(NTOK*NTOK) + t;
    const u64* Kp = (const u64*)Ks;
    const u64* Vp = (const u64*)Vs;

    float l = 0.f;
    u64 acc2[16];
    #pragma unroll
    for (int i = 0; i < 16; i++) acc2[i] = 0ull;

    #pragma unroll 2
    for (int j = 0; j < NTOK; j++) {
        const u64* kr = Kp + j*16;
        u64 sa = 0ull, sb = 0ull;
        #pragma unroll
        for (int i = 0; i < 8; i++) {
            fma2(sa, q2[2*i+0], kr[2*i+0]);
            fma2(sb, q2[2*i+1], kr[2*i+1]);
        }
        float2 ua = up2(sa), ub = up2(sb);
        float s = (ua.x + ub.x) + (ua.y + ub.y) + rp[j*NTOK];
        float p = __expf(s - M);
        l += p;
        u64 p2 = dup2(p);
        const u64* vr = Vp + j*16;
        #pragma unroll
        for (int i = 0; i < 16; i++)
            fma2(acc2[i], p2, vr[i]);
    }

    const float inv = 1.f / l;
    __nv_bfloat162* oh = (__nv_bfloat162*)(g_aoh + (size_t)(b*NTOK + t)*NC + h*DH);
    __nv_bfloat162* ol = (__nv_bfloat162*)(g_aol + (size_t)(b*NTOK + t)*NC + h*DH);
    #pragma unroll
    for (int i = 0; i < 16; i++) {
        float2 x = up2(acc2[i]);
        float v0 = x.x * inv, v1 = x.y * inv;
        __nv_bfloat16 h0 = __float2bfloat16(v0);
        __nv_bfloat16 h1 = __float2bfloat16(v1);
        __nv_bfloat16 l0 = __float2bfloat16(v0 - __bfloat162float(h0));
        __nv_bfloat16 l1 = __float2bfloat16(v1 - __bfloat162float(h1));
        oh[i] = __nv_bfloat162(h0, h1);
        ol[i] = __nv_bfloat162(l0, l1);
    }
}

// =========================== launcher ====================================
extern "C" void kernel_launch(void* const* d_in, const int* in_sizes, int n_in,
                              void* d_out, int out_size)
{
    const float* x      = (const float*)d_in[0];
    const float* qkv_w  = (const float*)d_in[1];
    const float* q_bias = (const float*)d_in[2];
    const float* v_bias = (const float*)d_in[3];
    const float* lscale = (const float*)d_in[4];
    const float* cpb_w1 = (const float*)d_in[5];
    const float* cpb_b1 = (const float*)d_in[6];
    const float* cpb_w2 = (const float*)d_in[7];
    const float* proj_w = (const float*)d_in[8];
    const float* proj_b = (const float*)d_in[9];
    const float* rtab   = (const float*)d_in[10];
    const int*   rpi    = (const int*)d_in[11];
    float* out = (float*)d_out;

    const int attn_smem = 2*BHD*(int)sizeof(float);
    cudaFuncSetAttribute(attn_kernel, cudaFuncAttributeMaxDynamicSharedMemorySize, attn_smem);

    // fp32 -> bf16 hi/lo splits (destination chosen in device code!)
    {
        int n4 = MROWS*NC/4;
        split_kernel<<<(n4+255)/256, 256>>>(x, n4, 0);
        int w4 = 1152*NC/4;
        split_kernel<<<(w4+255)/256, 256>>>(qkv_w, w4, 1);
        int p4 = NC*NC/4;
        split_kernel<<<(p4+255)/256, 256>>>(proj_w, p4, 2);
    }

    cpb_kernel<<<961, 512>>>(rtab, cpb_w1, cpb_b1, cpb_w2);
    gather_kernel<<<NTOK, NTOK>>>(rpi);

    dim3 gq(1152/128, MROWS/128);
    qkv_hm_kernel<<<gq, 256, HM_SMEM>>>(q_bias, v_bias);

    attn_kernel<<<NWIN*NH, 256, attn_smem>>>(lscale);

    dim3 gp(NC/128, MROWS/128);
    proj_hm_kernel<<<gp, 256, HM_SMEM>>>(proj_b, out);
}

// round 9
// speedup vs baseline: 1.7619x; 1.3235x over previous
#include <cuda_runtime.h>
#include <cuda_bf16.h>
#include <math.h>

// ---------------- problem constants ----------------
#define NWIN 256
#define NTOK 256
#define NC   384
#define NH   12
#define DH   32
#define MROWS (NWIN*NTOK)
#define BHD (NTOK*DH)

typedef unsigned long long u64;
typedef unsigned int u32;

// ---------------- mma helper (bf16, R7 silicon-verified) ------
__device__ __forceinline__ void mma16816(float c[4], const u32 a[4], u32 b0, u32 b1) {
    asm volatile(
        "mma.sync.aligned.m16n8k16.row.col.f32.bf16.bf16.f32 "
        "{%0,%1,%2,%3},{%4,%5,%6,%7},{%8,%9},{%0,%1,%2,%3};"
        : "+f"(c[0]), "+f"(c[1]), "+f"(c[2]), "+f"(c[3])
        : "r"(a[0]), "r"(a[1]), "r"(a[2]), "r"(a[3]), "r"(b0), "r"(b1));
}
__device__ __forceinline__ void splitb(float x, __nv_bfloat16& hh, __nv_bfloat16& hl) {
    hh = __float2bfloat16(x);
    hl = __float2bfloat16(x - __bfloat162float(hh));
}
// __nv_bfloat162(a,b): a -> low half (verified by R7 epilogue)
__device__ __forceinline__ u32 packb(__nv_bfloat16 a, __nv_bfloat16 b) {
    __nv_bfloat162 h(a, b);
    return *(u32*)&h;
}

// ---------------- scratch (referenced ONLY from device code) ----------
__device__ float g_q[(size_t)NWIN*NH*BHD];
__device__ float g_k[(size_t)NWIN*NH*BHD];
__device__ float g_v[(size_t)NWIN*NH*BHD];
__device__ float g_bt[961*NH];
__device__ float g_rpbT[(size_t)NH*NTOK*NTOK];   // [h][j][qi]
__device__ __align__(16) __nv_bfloat16 g_xh[(size_t)MROWS*NC];
__device__ __align__(16) __nv_bfloat16 g_xl[(size_t)MROWS*NC];
__device__ __align__(16) __nv_bfloat16 g_qwh[1152*NC];
__device__ __align__(16) __nv_bfloat16 g_qwl[1152*NC];
__device__ __align__(16) __nv_bfloat16 g_pwh[NC*NC];
__device__ __align__(16) __nv_bfloat16 g_pwl[NC*NC];
__device__ __align__(16) __nv_bfloat16 g_aoh[(size_t)MROWS*NC];
__device__ __align__(16) __nv_bfloat16 g_aol[(size_t)MROWS*NC];

// ================= split fp32 -> bf16 hi + lo (dst picked device-side) ==
__global__ void split_kernel(const float* __restrict__ src, int n4, int which)
{
    __nv_bfloat16* hi = (which == 0) ? g_xh : (which == 1) ? g_qwh : g_pwh;
    __nv_bfloat16* lo = (which == 0) ? g_xl : (which == 1) ? g_qwl : g_pwl;
    int i = blockIdx.x*blockDim.x + threadIdx.x;
    if (i >= n4) return;
    float4 v = ((const float4*)src)[i];
    float vals[4] = {v.x, v.y, v.z, v.w};
    __nv_bfloat16 h[4], l[4];
    #pragma unroll
    for (int j = 0; j < 4; j++) {
        h[j] = __float2bfloat16(vals[j]);
        l[j] = __float2bfloat16(vals[j] - __bfloat162float(h[j]));
    }
    ((__nv_bfloat162*)hi)[2*i+0] = __nv_bfloat162(h[0], h[1]);
    ((__nv_bfloat162*)hi)[2*i+1] = __nv_bfloat162(h[2], h[3]);
    ((__nv_bfloat162*)lo)[2*i+0] = __nv_bfloat162(l[0], l[1]);
    ((__nv_bfloat162*)lo)[2*i+1] = __nv_bfloat162(l[2], l[3]);
}

// ================= CPB MLP ==============
__global__ void cpb_kernel(const float* __restrict__ table,
                           const float* __restrict__ w1,
                           const float* __restrict__ b1,
                           const float* __restrict__ w2)
{
    __shared__ float sh[512];
    const int e = blockIdx.x;
    const int t = threadIdx.x;
    const float c0 = table[e*2+0], c1 = table[e*2+1];
    float hid = fmaf(c0, w1[t*2+0], fmaf(c1, w1[t*2+1], b1[t]));
    sh[t] = fmaxf(hid, 0.f);
    __syncthreads();
    const int w = t >> 5, l = t & 31;
    if (w < NH) {
        float s = 0.f;
        #pragma unroll
        for (int i = 0; i < 16; i++)
            s = fmaf(sh[l + i*32], w2[w*512 + l + i*32], s);
        #pragma unroll
        for (int o = 16; o > 0; o >>= 1)
            s += __shfl_xor_sync(0xffffffffu, s, o);
        if (l == 0) g_bt[e*NH + w] = s;
    }
}

__global__ void gather_kernel(const int* __restrict__ rpi)
{
    const int qi = threadIdx.x;
    const int j  = blockIdx.x;
    const int idx = rpi[qi*NTOK + j];
    #pragma unroll
    for (int h = 0; h < NH; h++) {
        float bv = g_bt[idx*NH + h];
        float sg = 16.f / (1.f + __expf(-bv));
        g_rpbT[((size_t)h*NTOK + j)*NTOK + qi] = sg;
    }
}

// ====================== HMMA bf16x3 GEMM mainloop (R7-proven) ===========
#define AS_STR 72
#define HM_SMEM (2*128*AS_STR*2)

__device__ __forceinline__ void hmma_mainloop(
    const __nv_bfloat16* __restrict__ Ah, const __nv_bfloat16* __restrict__ Al,
    const __nv_bfloat16* __restrict__ Bh, const __nv_bfloat16* __restrict__ Bl,
    int row0, int col0, __nv_bfloat16* As, __nv_bfloat16* Bs, float acc[4][4][4])
{
    const int t = threadIdx.x;
    const int r = t >> 1, hf = t & 1;

    const __nv_bfloat16* aH = Ah + (size_t)(row0 + r)*NC + hf*32;
    const __nv_bfloat16* aL = Al + (size_t)(row0 + r)*NC + hf*32;
    const __nv_bfloat16* bH = Bh + (size_t)(col0 + r)*NC + hf*32;
    const __nv_bfloat16* bL = Bl + (size_t)(col0 + r)*NC + hf*32;

    uint4 ra[4], rb[4];
    auto gload = [&](int kt) {
        const int seg = kt / 6;
        const int kk  = (kt - seg*6) * 64;
        const uint4* ap = (const uint4*)(((seg == 2) ? aL : aH) + kk);
        const uint4* bp = (const uint4*)(((seg == 1) ? bL : bH) + kk);
        #pragma unroll
        for (int j = 0; j < 4; j++) { ra[j] = ap[j]; rb[j] = bp[j]; }
    };

    const int wid = t >> 5, lane = t & 31;
    const int wm = wid & 1, wn = wid >> 1;
    const int gid = lane >> 2, tig = lane & 3;

    gload(0);

    #pragma unroll 1
    for (int kt = 0; kt < 18; kt++) {
        __nv_bfloat16* as = As + r*AS_STR + hf*32;
        __nv_bfloat16* bs = Bs + r*AS_STR + hf*32;
        #pragma unroll
        for (int j = 0; j < 4; j++) {
            *(uint4*)(as + j*8) = ra[j];
            *(uint4*)(bs + j*8) = rb[j];
        }
        __syncthreads();
        if (kt < 17) gload(kt + 1);

        #pragma unroll
        for (int ks = 0; ks < 4; ks++) {
            const int k0 = ks*16 + tig*2;
            u32 a[4][4];
            #pragma unroll
            for (int mf = 0; mf < 4; mf++) {
                const int rb_ = wm*64 + mf*16 + gid;
                a[mf][0] = *(const u32*)&As[rb_*AS_STR + k0];
                a[mf][1] = *(const u32*)&As[(rb_+8)*AS_STR + k0];
                a[mf][2] = *(const u32*)&As[rb_*AS_STR + k0 + 8];
                a[mf][3] = *(const u32*)&As[(rb_+8)*AS_STR + k0 + 8];
            }
            u32 b[4][2];
            #pragma unroll
            for (int nf = 0; nf < 4; nf++) {
                const int nb = wn*32 + nf*8 + gid;
                b[nf][0] = *(const u32*)&Bs[nb*AS_STR + k0];
                b[nf][1] = *(const u32*)&Bs[nb*AS_STR + k0 + 8];
            }
            #pragma unroll
            for (int mf = 0; mf < 4; mf++)
                #pragma unroll
                for (int nf = 0; nf < 4; nf++)
                    mma16816(acc[mf][nf], a[mf], b[nf][0], b[nf][1]);
        }
        __syncthreads();
    }
}

// ================= QKV GEMM (HMMA) ===========
__global__ __launch_bounds__(256, 2) void qkv_hm_kernel(
    const float* __restrict__ qb, const float* __restrict__ vb)
{
    extern __shared__ __nv_bfloat16 smbf[];
    __nv_bfloat16* As = smbf;
    __nv_bfloat16* Bs = smbf + 128*AS_STR;
    const int row0 = blockIdx.y * 128;
    const int col0 = blockIdx.x * 128;

    float acc[4][4][4];
    #pragma unroll
    for (int i = 0; i < 4; i++)
        #pragma unroll
        for (int j = 0; j < 4; j++)
            #pragma unroll
            for (int k = 0; k < 4; k++) acc[i][j][k] = 0.f;

    hmma_mainloop(g_xh, g_xl, g_qwh, g_qwl, row0, col0, As, Bs, acc);

    const int t = threadIdx.x;
    const int wid = t >> 5, lane = t & 31;
    const int wm = wid & 1, wn = wid >> 1;
    const int r_in = lane >> 2, c_in = (lane & 3)*2;

    #pragma unroll
    for (int nf = 0; nf < 4; nf++) {
        const int cg = col0 + wn*32 + nf*8 + c_in;
        const int which = cg / NC;
        const int cw = cg % NC;
        const int hh = cw >> 5, d0 = cw & 31;
        const float b0 = (which == 0) ? qb[cw]   : (which == 2) ? vb[cw]   : 0.f;
        const float b1 = (which == 0) ? qb[cw+1] : (which == 2) ? vb[cw+1] : 0.f;
        float* base = (which == 0) ? g_q : (which == 1) ? g_k : g_v;
        #pragma unroll
        for (int mf = 0; mf < 4; mf++) {
            int m0 = row0 + wm*64 + mf*16 + r_in;
            int bb = m0 >> 8, nn = m0 & 255;
            float* p = base + ((((size_t)bb*NH + hh)*NTOK) + nn)*DH + d0;
            *(float2*)p = make_float2(acc[mf][nf][0] + b0, acc[mf][nf][1] + b1);
            int m1 = m0 + 8; bb = m1 >> 8; nn = m1 & 255;
            p = base + ((((size_t)bb*NH + hh)*NTOK) + nn)*DH + d0;
            *(float2*)p = make_float2(acc[mf][nf][2] + b0, acc[mf][nf][3] + b1);
        }
    }
}

// ================= Proj GEMM (HMMA) ===========
__global__ __launch_bounds__(256, 2) void proj_hm_kernel(
    const float* __restrict__ pb, float* __restrict__ out)
{
    extern __shared__ __nv_bfloat16 smbf[];
    __nv_bfloat16* As = smbf;
    __nv_bfloat16* Bs = smbf + 128*AS_STR;
    const int row0 = blockIdx.y * 128;
    const int col0 = blockIdx.x * 128;

    float acc[4][4][4];
    #pragma unroll
    for (int i = 0; i < 4; i++)
        #pragma unroll
        for (int j = 0; j < 4; j++)
            #pragma unroll
            for (int k = 0; k < 4; k++) acc[i][j][k] = 0.f;

    hmma_mainloop(g_aoh, g_aol, g_pwh, g_pwl, row0, col0, As, Bs, acc);

    const int t = threadIdx.x;
    const int wid = t >> 5, lane = t & 31;
    const int wm = wid & 1, wn = wid >> 1;
    const int r_in = lane >> 2, c_in = (lane & 3)*2;

    #pragma unroll
    for (int nf = 0; nf < 4; nf++) {
        const int cg = col0 + wn*32 + nf*8 + c_in;
        const float b0 = pb[cg], b1 = pb[cg+1];
        #pragma unroll
        for (int mf = 0; mf < 4; mf++) {
            int m0 = row0 + wm*64 + mf*16 + r_in;
            *(float2*)(out + (size_t)m0*NC + cg) =
                make_float2(acc[mf][nf][0] + b0, acc[mf][nf][1] + b1);
            *(float2*)(out + (size_t)(m0+8)*NC + cg) =
                make_float2(acc[mf][nf][2] + b0, acc[mf][nf][3] + b1);
        }
    }
}

// ================= Attention (HMMA bf16x3, static-shift softmax) =========
// smem (bf16 units): Qh[256*40] Ql[256*40] Kh[256*40] Kl[256*40]
//                    Vht[32*264] Vlt[32*264]  (V transposed [dim][key])
#define QSTR 40
#define VSTR 264
#define SQH 0
#define SQL 10240
#define SKH 20480
#define SKL 30720
#define SVH 40960
#define SVL 49408
#define ATT_SMEM ((49408 + 32*VSTR) * 2)   // 115712 B

__global__ __launch_bounds__(256) void attn_kernel(const float* __restrict__ logit_scale)
{
    extern __shared__ __nv_bfloat16 smb[];
    const int bh = blockIdx.x;
    const int h  = bh % NH;
    const int b  = bh / NH;
    const int t  = threadIdx.x;
    const int wid = t >> 5, lane = t & 31;
    const int gid = lane >> 2, tig = lane & 3;

    const float sc = __expf(fminf(logit_scale[h], 4.6051702f));
    const float M  = sc + 16.f;

    // ---- setup: thread t handles row t of K, Q, V ----
    {
        float v[DH]; float s;
        // K row: normalize, bf16 split
        const float* p = g_k + (size_t)bh*BHD + t*DH;
        s = 0.f;
        #pragma unroll
        for (int d = 0; d < DH; d += 4) {
            float4 f = *(const float4*)(p + d);
            v[d]=f.x; v[d+1]=f.y; v[d+2]=f.z; v[d+3]=f.w;
        }
        #pragma unroll
        for (int d = 0; d < DH; d++) s = fmaf(v[d], v[d], s);
        float inv = 1.f / fmaxf(sqrtf(s), 1e-12f);
        #pragma unroll
        for (int i = 0; i < 16; i++) {
            __nv_bfloat16 h0,l0,h1,l1;
            splitb(v[2*i]*inv, h0, l0);
            splitb(v[2*i+1]*inv, h1, l1);
            *(u32*)&smb[SKH + t*QSTR + 2*i] = packb(h0, h1);
            *(u32*)&smb[SKL + t*QSTR + 2*i] = packb(l0, l1);
        }
        // Q row: normalize * sc, bf16 split
        p = g_q + (size_t)bh*BHD + t*DH;
        s = 0.f;
        #pragma unroll
        for (int d = 0; d < DH; d += 4) {
            float4 f = *(const float4*)(p + d);
            v[d]=f.x; v[d+1]=f.y; v[d+2]=f.z; v[d+3]=f.w;
        }
        #pragma unroll
        for (int d = 0; d < DH; d++) s = fmaf(v[d], v[d], s);
        inv = sc / fmaxf(sqrtf(s), 1e-12f);
        #pragma unroll
        for (int i = 0; i < 16; i++) {
            __nv_bfloat16 h0,l0,h1,l1;
            splitb(v[2*i]*inv, h0, l0);
            splitb(v[2*i+1]*inv, h1, l1);
            *(u32*)&smb[SQH + t*QSTR + 2*i] = packb(h0, h1);
            *(u32*)&smb[SQL + t*QSTR + 2*i] = packb(l0, l1);
        }
        // V row: bf16 split, transposed elementwise store [dim][key]
        p = g_v + (size_t)bh*BHD + t*DH;
        #pragma unroll
        for (int d = 0; d < DH; d += 4) {
            float4 f = *(const float4*)(p + d);
            v[d]=f.x; v[d+1]=f.y; v[d+2]=f.z; v[d+3]=f.w;
        }
        #pragma unroll
        for (int d = 0; d < DH; d++) {
            __nv_bfloat16 h0,l0;
            splitb(v[d], h0, l0);
            smb[SVH + d*VSTR + t] = h0;
            smb[SVL + d*VSTR + t] = l0;
        }
    }
    __syncthreads();

    // ---- persistent Q a-frags ----
    u32 qh[2][2][4], ql[2][2][4];
    #pragma unroll
    for (int mt = 0; mt < 2; mt++)
        #pragma unroll
        for (int ks = 0; ks < 2; ks++) {
            const int row = wid*32 + mt*16 + gid;
            const int k0  = ks*16 + 2*tig;
            qh[mt][ks][0] = *(const u32*)&smb[SQH + row*QSTR + k0];
            qh[mt][ks][1] = *(const u32*)&smb[SQH + (row+8)*QSTR + k0];
            qh[mt][ks][2] = *(const u32*)&smb[SQH + row*QSTR + k0 + 8];
            qh[mt][ks][3] = *(const u32*)&smb[SQH + (row+8)*QSTR + k0 + 8];
            ql[mt][ks][0] = *(const u32*)&smb[SQL + row*QSTR + k0];
            ql[mt][ks][1] = *(const u32*)&smb[SQL + (row+8)*QSTR + k0];
            ql[mt][ks][2] = *(const u32*)&smb[SQL + row*QSTR + k0 + 8];
            ql[mt][ks][3] = *(const u32*)&smb[SQL + (row+8)*QSTR + k0 + 8];
        }

    float acc[2][4][4];
    #pragma unroll
    for (int i = 0; i < 2; i++)
        #pragma unroll
        for (int j = 0; j < 4; j++)
            #pragma unroll
            for (int k = 0; k < 4; k++) acc[i][j][k] = 0.f;
    float lsum[4] = {0.f, 0.f, 0.f, 0.f};

    const float* rp = g_rpbT + (size_t)h*(NTOK*NTOK);

    #pragma unroll 1
    for (int kt = 0; kt < 16; kt++) {
        // rpb prefetch
        float rb[2][2][4];
        #pragma unroll
        for (int mt = 0; mt < 2; mt++)
            #pragma unroll
            for (int n8 = 0; n8 < 2; n8++) {
                const int col = kt*16 + n8*8 + 2*tig;
                const int row = wid*32 + mt*16 + gid;
                rb[mt][n8][0] = rp[col*NTOK + row];
                rb[mt][n8][1] = rp[(col+1)*NTOK + row];
                rb[mt][n8][2] = rp[col*NTOK + row + 8];
                rb[mt][n8][3] = rp[(col+1)*NTOK + row + 8];
            }

        // K b-frags
        u32 kbh[2][2][2], kbl[2][2][2];
        #pragma unroll
        for (int n8 = 0; n8 < 2; n8++)
            #pragma unroll
            for (int ks = 0; ks < 2; ks++) {
                const int key = kt*16 + n8*8 + gid;
                const int k0  = ks*16 + 2*tig;
                kbh[n8][ks][0] = *(const u32*)&smb[SKH + key*QSTR + k0];
                kbh[n8][ks][1] = *(const u32*)&smb[SKH + key*QSTR + k0 + 8];
                kbl[n8][ks][0] = *(const u32*)&smb[SKL + key*QSTR + k0];
                kbl[n8][ks][1] = *(const u32*)&smb[SKL + key*QSTR + k0 + 8];
            }

        // S = (Qhat*sc) @ Khat^T  (bf16 3-term)
        float c[2][2][4];
        #pragma unroll
        for (int i = 0; i < 2; i++)
            #pragma unroll
            for (int j = 0; j < 2; j++)
                #pragma unroll
                for (int k = 0; k < 4; k++) c[i][j][k] = 0.f;
        #pragma unroll
        for (int mt = 0; mt < 2; mt++)
            #pragma unroll
            for (int n8 = 0; n8 < 2; n8++)
                #pragma unroll
                for (int ks = 0; ks < 2; ks++) {
                    mma16816(c[mt][n8], qh[mt][ks], kbh[n8][ks][0], kbh[n8][ks][1]);
                    mma16816(c[mt][n8], qh[mt][ks], kbl[n8][ks][0], kbl[n8][ks][1]);
                    mma16816(c[mt][n8], ql[mt][ks], kbh[n8][ks][0], kbh[n8][ks][1]);
                }

        // softmax numerator with static shift M
        #pragma unroll
        for (int mt = 0; mt < 2; mt++)
            #pragma unroll
            for (int n8 = 0; n8 < 2; n8++)
                #pragma unroll
                for (int e = 0; e < 4; e++) {
                    float pv = __expf(c[mt][n8][e] + rb[mt][n8][e] - M);
                    lsum[mt*2 + (e>>1)] += pv;
                    c[mt][n8][e] = pv;
                }

        // P -> bf16-split A-frags (c-frag -> a-frag identity)
        u32 ah[2][4], al[2][4];
        #pragma unroll
        for (int mt = 0; mt < 2; mt++) {
            __nv_bfloat16 h0,l0,h1,l1;
            splitb(c[mt][0][0], h0, l0); splitb(c[mt][0][1], h1, l1);
            ah[mt][0] = packb(h0,h1); al[mt][0] = packb(l0,l1);
            splitb(c[mt][0][2], h0, l0); splitb(c[mt][0][3], h1, l1);
            ah[mt][1] = packb(h0,h1); al[mt][1] = packb(l0,l1);
            splitb(c[mt][1][0], h0, l0); splitb(c[mt][1][1], h1, l1);
            ah[mt][2] = packb(h0,h1); al[mt][2] = packb(l0,l1);
            splitb(c[mt][1][2], h0, l0); splitb(c[mt][1][3], h1, l1);
            ah[mt][3] = packb(h0,h1); al[mt][3] = packb(l0,l1);
        }

        // PV  (bf16 3-term)
        #pragma unroll
        for (int n8d = 0; n8d < 4; n8d++) {
            const int dim = n8d*8 + gid;
            const int k0  = kt*16 + 2*tig;
            u32 vh0 = *(const u32*)&smb[SVH + dim*VSTR + k0];
            u32 vh1 = *(const u32*)&smb[SVH + dim*VSTR + k0 + 8];
            u32 vl0 = *(const u32*)&smb[SVL + dim*VSTR + k0];
            u32 vl1 = *(const u32*)&smb[SVL + dim*VSTR + k0 + 8];
            #pragma unroll
            for (int mt = 0; mt < 2; mt++) {
                mma16816(acc[mt][n8d], ah[mt], vh0, vh1);
                mma16816(acc[mt][n8d], ah[mt], vl0, vl1);
                mma16816(acc[mt][n8d], al[mt], vh0, vh1);
            }
        }
    }

    // ---- epilogue: reduce l over quad, scale, write bf16 hi/lo ----
    #pragma unroll
    for (int i = 0; i < 4; i++) {
        lsum[i] += __shfl_xor_sync(0xffffffffu, lsum[i], 1);
        lsum[i] += __shfl_xor_sync(0xffffffffu, lsum[i], 2);
        lsum[i] = 1.f / lsum[i];
    }

    #pragma unroll
    for (int mt = 0; mt < 2; mt++)
        #pragma unroll
        for (int n8d = 0; n8d < 4; n8d++) {
            const int row0 = wid*32 + mt*16 + gid;
            const int dim  = n8d*8 + 2*tig;
            const float i0 = lsum[mt*2], i1 = lsum[mt*2+1];
            float v0 = acc[mt][n8d][0]*i0, v1 = acc[mt][n8d][1]*i0;
            float v2 = acc[mt][n8d][2]*i1, v3 = acc[mt][n8d][3]*i1;
            size_t o0 = ((size_t)(b*NTOK + row0))*NC + h*DH + dim;
            size_t o1 = ((size_t)(b*NTOK + row0 + 8))*NC + h*DH + dim;
            __nv_bfloat16 b0 = __float2bfloat16(v0), b1 = __float2bfloat16(v1);
            __nv_bfloat16 b2 = __float2bfloat16(v2), b3 = __float2bfloat16(v3);
            *(__nv_bfloat162*)&g_aoh[o0] = __nv_bfloat162(b0, b1);
            *(__nv_bfloat162*)&g_aoh[o1] = __nv_bfloat162(b2, b3);
            *(__nv_bfloat162*)&g_aol[o0] = __nv_bfloat162(
                __float2bfloat16(v0 - __bfloat162float(b0)),
                __float2bfloat16(v1 - __bfloat162float(b1)));
            *(__nv_bfloat162*)&g_aol[o1] = __nv_bfloat162(
                __float2bfloat16(v2 - __bfloat162float(b2)),
                __float2bfloat16(v3 - __bfloat162float(b3)));
        }
}

// =========================== launcher ====================================
extern "C" void kernel_launch(void* const* d_in, const int* in_sizes, int n_in,
                              void* d_out, int out_size)
{
    const float* x      = (const float*)d_in[0];
    const float* qkv_w  = (const float*)d_in[1];
    const float* q_bias = (const float*)d_in[2];
    const float* v_bias = (const float*)d_in[3];
    const float* lscale = (const float*)d_in[4];
    const float* cpb_w1 = (const float*)d_in[5];
    const float* cpb_b1 = (const float*)d_in[6];
    const float* cpb_w2 = (const float*)d_in[7];
    const float* proj_w = (const float*)d_in[8];
    const float* proj_b = (const float*)d_in[9];
    const float* rtab   = (const float*)d_in[10];
    const int*   rpi    = (const int*)d_in[11];
    float* out = (float*)d_out;

    cudaFuncSetAttribute(attn_kernel, cudaFuncAttributeMaxDynamicSharedMemorySize, ATT_SMEM);

    {
        int n4 = MROWS*NC/4;
        split_kernel<<<(n4+255)/256, 256>>>(x, n4, 0);
        int w4 = 1152*NC/4;
        split_kernel<<<(w4+255)/256, 256>>>(qkv_w, w4, 1);
        int p4 = NC*NC/4;
        split_kernel<<<(p4+255)/256, 256>>>(proj_w, p4, 2);
    }

    cpb_kernel<<<961, 512>>>(rtab, cpb_w1, cpb_b1, cpb_w2);
    gather_kernel<<<NTOK, NTOK>>>(rpi);

    dim3 gq(1152/128, MROWS/128);
    qkv_hm_kernel<<<gq, 256, HM_SMEM>>>(q_bias, v_bias);

    attn_kernel<<<NWIN*NH, 256, ATT_SMEM>>>(lscale);

    dim3 gp(NC/128, MROWS/128);
    proj_hm_kernel<<<gp, 256, HM_SMEM>>>(proj_b, out);
}

// round 10
// speedup vs baseline: 1.9908x; 1.1300x over previous
#include <cuda_runtime.h>
#include <cuda_bf16.h>
#include <math.h>

// ---------------- problem constants ----------------
#define NWIN 256
#define NTOK 256
#define NC   384
#define NH   12
#define DH   32
#define MROWS (NWIN*NTOK)
#define BHD (NTOK*DH)

typedef unsigned long long u64;
typedef unsigned int u32;

// ---------------- mma / ldmatrix helpers ------
__device__ __forceinline__ void mma16816(float c[4], const u32 a[4], u32 b0, u32 b1) {
    asm volatile(
        "mma.sync.aligned.m16n8k16.row.col.f32.bf16.bf16.f32 "
        "{%0,%1,%2,%3},{%4,%5,%6,%7},{%8,%9},{%0,%1,%2,%3};"
        : "+f"(c[0]), "+f"(c[1]), "+f"(c[2]), "+f"(c[3])
        : "r"(a[0]), "r"(a[1]), "r"(a[2]), "r"(a[3]), "r"(b0), "r"(b1));
}
__device__ __forceinline__ void ldmx4(u32 r[4], u32 addr) {
    asm volatile("ldmatrix.sync.aligned.m8n8.x4.shared.b16 {%0,%1,%2,%3}, [%4];"
        : "=r"(r[0]), "=r"(r[1]), "=r"(r[2]), "=r"(r[3]) : "r"(addr));
}
__device__ __forceinline__ u32 smem_to_u32(const void* p) {
    u32 a;
    asm("{ .reg .u64 t; cvta.to.shared.u64 t, %1; cvt.u32.u64 %0, t; }" : "=r"(a) : "l"(p));
    return a;
}
__device__ __forceinline__ void splitb(float x, __nv_bfloat16& hh, __nv_bfloat16& hl) {
    hh = __float2bfloat16(x);
    hl = __float2bfloat16(x - __bfloat162float(hh));
}
__device__ __forceinline__ u32 packb(__nv_bfloat16 a, __nv_bfloat16 b) {
    __nv_bfloat162 h(a, b);
    return *(u32*)&h;
}

// ---------------- scratch (referenced ONLY from device code) ----------
__device__ float g_q[(size_t)NWIN*NH*BHD];
__device__ float g_k[(size_t)NWIN*NH*BHD];
__device__ float g_v[(size_t)NWIN*NH*BHD];
__device__ float g_bt[961*NH];
__device__ float g_rpbT[(size_t)NH*NTOK*NTOK];   // [h][j][qi]
__device__ __align__(16) __nv_bfloat16 g_xh[(size_t)MROWS*NC];
__device__ __align__(16) __nv_bfloat16 g_xl[(size_t)MROWS*NC];
__device__ __align__(16) __nv_bfloat16 g_qwh[1152*NC];
__device__ __align__(16) __nv_bfloat16 g_qwl[1152*NC];
__device__ __align__(16) __nv_bfloat16 g_pwh[NC*NC];
__device__ __align__(16) __nv_bfloat16 g_pwl[NC*NC];
__device__ __align__(16) __nv_bfloat16 g_aoh[(size_t)MROWS*NC];
__device__ __align__(16) __nv_bfloat16 g_aol[(size_t)MROWS*NC];

// ================= split fp32 -> bf16 hi + lo (dst picked device-side) ==
__global__ void split_kernel(const float* __restrict__ src, int n4, int which)
{
    __nv_bfloat16* hi = (which == 0) ? g_xh : (which == 1) ? g_qwh : g_pwh;
    __nv_bfloat16* lo = (which == 0) ? g_xl : (which == 1) ? g_qwl : g_pwl;
    int i = blockIdx.x*blockDim.x + threadIdx.x;
    if (i >= n4) return;
    float4 v = ((const float4*)src)[i];
    float vals[4] = {v.x, v.y, v.z, v.w};
    __nv_bfloat16 h[4], l[4];
    #pragma unroll
    for (int j = 0; j < 4; j++) {
        h[j] = __float2bfloat16(vals[j]);
        l[j] = __float2bfloat16(vals[j] - __bfloat162float(h[j]));
    }
    ((__nv_bfloat162*)hi)[2*i+0] = __nv_bfloat162(h[0], h[1]);
    ((__nv_bfloat162*)hi)[2*i+1] = __nv_bfloat162(h[2], h[3]);
    ((__nv_bfloat162*)lo)[2*i+0] = __nv_bfloat162(l[0], l[1]);
    ((__nv_bfloat162*)lo)[2*i+1] = __nv_bfloat162(l[2], l[3]);
}

// ================= CPB MLP ==============
__global__ void cpb_kernel(const float* __restrict__ table,
                           const float* __restrict__ w1,
                           const float* __restrict__ b1,
                           const float* __restrict__ w2)
{
    __shared__ float sh[512];
    const int e = blockIdx.x;
    const int t = threadIdx.x;
    const float c0 = table[e*2+0], c1 = table[e*2+1];
    float hid = fmaf(c0, w1[t*2+0], fmaf(c1, w1[t*2+1], b1[t]));
    sh[t] = fmaxf(hid, 0.f);
    __syncthreads();
    const int w = t >> 5, l = t & 31;
    if (w < NH) {
        float s = 0.f;
        #pragma unroll
        for (int i = 0; i < 16; i++)
            s = fmaf(sh[l + i*32], w2[w*512 + l + i*32], s);
        #pragma unroll
        for (int o = 16; o > 0; o >>= 1)
            s += __shfl_xor_sync(0xffffffffu, s, o);
        if (l == 0) g_bt[e*NH + w] = s;
    }
}

__global__ void gather_kernel(const int* __restrict__ rpi)
{
    const int qi = threadIdx.x;
    const int j  = blockIdx.x;
    const int idx = rpi[qi*NTOK + j];
    #pragma unroll
    for (int h = 0; h < NH; h++) {
        float bv = g_bt[idx*NH + h];
        float sg = 16.f / (1.f + __expf(-bv));
        g_rpbT[((size_t)h*NTOK + j)*NTOK + qi] = sg;
    }
}

// ====================== HMMA bf16x3 GEMM mainloop (+ldmatrix) ===========
#define AS_STR 72
#define HM_SMEM (2*128*AS_STR*2)

__device__ __forceinline__ void hmma_mainloop(
    const __nv_bfloat16* __restrict__ Ah, const __nv_bfloat16* __restrict__ Al,
    const __nv_bfloat16* __restrict__ Bh, const __nv_bfloat16* __restrict__ Bl,
    int row0, int col0, __nv_bfloat16* As, __nv_bfloat16* Bs, float acc[4][4][4])
{
    const int t = threadIdx.x;
    const int r = t >> 1, hf = t & 1;

    const __nv_bfloat16* aH = Ah + (size_t)(row0 + r)*NC + hf*32;
    const __nv_bfloat16* aL = Al + (size_t)(row0 + r)*NC + hf*32;
    const __nv_bfloat16* bH = Bh + (size_t)(col0 + r)*NC + hf*32;
    const __nv_bfloat16* bL = Bl + (size_t)(col0 + r)*NC + hf*32;

    uint4 ra[4], rb[4];
    auto gload = [&](int kt) {
        const int seg = kt / 6;
        const int kk  = (kt - seg*6) * 64;
        const uint4* ap = (const uint4*)(((seg == 2) ? aL : aH) + kk);
        const uint4* bp = (const uint4*)(((seg == 1) ? bL : bH) + kk);
        #pragma unroll
        for (int j = 0; j < 4; j++) { ra[j] = ap[j]; rb[j] = bp[j]; }
    };

    const int wid = t >> 5, lane = t & 31;
    const int wm = wid & 1, wn = wid >> 1;

    // ldmatrix lane-derived offsets
    const int a_rr = lane & 15;               // A row within m16
    const int a_q  = (lane >> 4) << 3;        // A k-half (0/8)
    const int b_no = ((lane >> 4) << 3) + (lane & 7);   // B n offset within nf-pair
    const int b_ko = ((lane >> 3) & 1) << 3;            // B k-half (0/8)
    const u32 sA = smem_to_u32(As);
    const u32 sB = smem_to_u32(Bs);

    gload(0);

    #pragma unroll 1
    for (int kt = 0; kt < 18; kt++) {
        __nv_bfloat16* as = As + r*AS_STR + hf*32;
        __nv_bfloat16* bs = Bs + r*AS_STR + hf*32;
        #pragma unroll
        for (int j = 0; j < 4; j++) {
            *(uint4*)(as + j*8) = ra[j];
            *(uint4*)(bs + j*8) = rb[j];
        }
        __syncthreads();
        if (kt < 17) gload(kt + 1);

        #pragma unroll
        for (int ks = 0; ks < 4; ks++) {
            u32 a[4][4];
            #pragma unroll
            for (int mf = 0; mf < 4; mf++)
                ldmx4(a[mf], sA + ((wm*64 + mf*16 + a_rr)*AS_STR + ks*16 + a_q)*2);
            u32 b[4][2];
            #pragma unroll
            for (int nfp = 0; nfp < 2; nfp++) {
                u32 tmp[4];
                ldmx4(tmp, sB + ((wn*32 + nfp*16 + b_no)*AS_STR + ks*16 + b_ko)*2);
                b[2*nfp+0][0] = tmp[0]; b[2*nfp+0][1] = tmp[1];
                b[2*nfp+1][0] = tmp[2]; b[2*nfp+1][1] = tmp[3];
            }
            #pragma unroll
            for (int mf = 0; mf < 4; mf++)
                #pragma unroll
                for (int nf = 0; nf < 4; nf++)
                    mma16816(acc[mf][nf], a[mf], b[nf][0], b[nf][1]);
        }
        __syncthreads();
    }
}

// ================= QKV GEMM (HMMA) ===========
__global__ __launch_bounds__(256, 2) void qkv_hm_kernel(
    const float* __restrict__ qb, const float* __restrict__ vb)
{
    extern __shared__ __nv_bfloat16 smbf[];
    __nv_bfloat16* As = smbf;
    __nv_bfloat16* Bs = smbf + 128*AS_STR;
    const int row0 = blockIdx.y * 128;
    const int col0 = blockIdx.x * 128;

    float acc[4][4][4];
    #pragma unroll
    for (int i = 0; i < 4; i++)
        #pragma unroll
        for (int j = 0; j < 4; j++)
            #pragma unroll
            for (int k = 0; k < 4; k++) acc[i][j][k] = 0.f;

    hmma_mainloop(g_xh, g_xl, g_qwh, g_qwl, row0, col0, As, Bs, acc);

    const int t = threadIdx.x;
    const int wid = t >> 5, lane = t & 31;
    const int wm = wid & 1, wn = wid >> 1;
    const int r_in = lane >> 2, c_in = (lane & 3)*2;

    #pragma unroll
    for (int nf = 0; nf < 4; nf++) {
        const int cg = col0 + wn*32 + nf*8 + c_in;
        const int which = cg / NC;
        const int cw = cg % NC;
        const int hh = cw >> 5, d0 = cw & 31;
        const float b0 = (which == 0) ? qb[cw]   : (which == 2) ? vb[cw]   : 0.f;
        const float b1 = (which == 0) ? qb[cw+1] : (which == 2) ? vb[cw+1] : 0.f;
        float* base = (which == 0) ? g_q : (which == 1) ? g_k : g_v;
        #pragma unroll
        for (int mf = 0; mf < 4; mf++) {
            int m0 = row0 + wm*64 + mf*16 + r_in;
            int bb = m0 >> 8, nn = m0 & 255;
            float* p = base + ((((size_t)bb*NH + hh)*NTOK) + nn)*DH + d0;
            *(float2*)p = make_float2(acc[mf][nf][0] + b0, acc[mf][nf][1] + b1);
            int m1 = m0 + 8; bb = m1 >> 8; nn = m1 & 255;
            p = base + ((((size_t)bb*NH + hh)*NTOK) + nn)*DH + d0;
            *(float2*)p = make_float2(acc[mf][nf][2] + b0, acc[mf][nf][3] + b1);
        }
    }
}

// ================= Proj GEMM (HMMA) ===========
__global__ __launch_bounds__(256, 2) void proj_hm_kernel(
    const float* __restrict__ pb, float* __restrict__ out)
{
    extern __shared__ __nv_bfloat16 smbf[];
    __nv_bfloat16* As = smbf;
    __nv_bfloat16* Bs = smbf + 128*AS_STR;
    const int row0 = blockIdx.y * 128;
    const int col0 = blockIdx.x * 128;

    float acc[4][4][4];
    #pragma unroll
    for (int i = 0; i < 4; i++)
        #pragma unroll
        for (int j = 0; j < 4; j++)
            #pragma unroll
            for (int k = 0; k < 4; k++) acc[i][j][k] = 0.f;

    hmma_mainloop(g_aoh, g_aol, g_pwh, g_pwl, row0, col0, As, Bs, acc);

    const int t = threadIdx.x;
    const int wid = t >> 5, lane = t & 31;
    const int wm = wid & 1, wn = wid >> 1;
    const int r_in = lane >> 2, c_in = (lane & 3)*2;

    #pragma unroll
    for (int nf = 0; nf < 4; nf++) {
        const int cg = col0 + wn*32 + nf*8 + c_in;
        const float b0 = pb[cg], b1 = pb[cg+1];
        #pragma unroll
        for (int mf = 0; mf < 4; mf++) {
            int m0 = row0 + wm*64 + mf*16 + r_in;
            *(float2*)(out + (size_t)m0*NC + cg) =
                make_float2(acc[mf][nf][0] + b0, acc[mf][nf][1] + b1);
            *(float2*)(out + (size_t)(m0+8)*NC + cg) =
                make_float2(acc[mf][nf][2] + b0, acc[mf][nf][3] + b1);
        }
    }
}

// ================= Attention (HMMA bf16x3, R9-proven) =========
#define QSTR 40
#define VSTR 264
#define SQH 0
#define SQL 10240
#define SKH 20480
#define SKL 30720
#define SVH 40960
#define SVL 49408
#define ATT_SMEM ((49408 + 32*VSTR) * 2)   // 115712 B

__global__ __launch_bounds__(256) void attn_kernel(const float* __restrict__ logit_scale)
{
    extern __shared__ __nv_bfloat16 smb[];
    const int bh = blockIdx.x;
    const int h  = bh % NH;
    const int b  = bh / NH;
    const int t  = threadIdx.x;
    const int wid = t >> 5, lane = t & 31;
    const int gid = lane >> 2, tig = lane & 3;

    const float sc = __expf(fminf(logit_scale[h], 4.6051702f));
    const float M  = sc + 16.f;

    // ---- setup ----
    {
        float v[DH]; float s;
        const float* p = g_k + (size_t)bh*BHD + t*DH;
        s = 0.f;
        #pragma unroll
        for (int d = 0; d < DH; d += 4) {
            float4 f = *(const float4*)(p + d);
            v[d]=f.x; v[d+1]=f.y; v[d+2]=f.z; v[d+3]=f.w;
        }
        #pragma unroll
        for (int d = 0; d < DH; d++) s = fmaf(v[d], v[d], s);
        float inv = 1.f / fmaxf(sqrtf(s), 1e-12f);
        #pragma unroll
        for (int i = 0; i < 16; i++) {
            __nv_bfloat16 h0,l0,h1,l1;
            splitb(v[2*i]*inv, h0, l0);
            splitb(v[2*i+1]*inv, h1, l1);
            *(u32*)&smb[SKH + t*QSTR + 2*i] = packb(h0, h1);
            *(u32*)&smb[SKL + t*QSTR + 2*i] = packb(l0, l1);
        }
        p = g_q + (size_t)bh*BHD + t*DH;
        s = 0.f;
        #pragma unroll
        for (int d = 0; d < DH; d += 4) {
            float4 f = *(const float4*)(p + d);
            v[d]=f.x; v[d+1]=f.y; v[d+2]=f.z; v[d+3]=f.w;
        }
        #pragma unroll
        for (int d = 0; d < DH; d++) s = fmaf(v[d], v[d], s);
        inv = sc / fmaxf(sqrtf(s), 1e-12f);
        #pragma unroll
        for (int i = 0; i < 16; i++) {
            __nv_bfloat16 h0,l0,h1,l1;
            splitb(v[2*i]*inv, h0, l0);
            splitb(v[2*i+1]*inv, h1, l1);
            *(u32*)&smb[SQH + t*QSTR + 2*i] = packb(h0, h1);
            *(u32*)&smb[SQL + t*QSTR + 2*i] = packb(l0, l1);
        }
        p = g_v + (size_t)bh*BHD + t*DH;
        #pragma unroll
        for (int d = 0; d < DH; d += 4) {
            float4 f = *(const float4*)(p + d);
            v[d]=f.x; v[d+1]=f.y; v[d+2]=f.z; v[d+3]=f.w;
        }
        #pragma unroll
        for (int d = 0; d < DH; d++) {
            __nv_bfloat16 h0,l0;
            splitb(v[d], h0, l0);
            smb[SVH + d*VSTR + t] = h0;
            smb[SVL + d*VSTR + t] = l0;
        }
    }
    __syncthreads();

    // ---- persistent Q a-frags ----
    u32 qh[2][2][4], ql[2][2][4];
    #pragma unroll
    for (int mt = 0; mt < 2; mt++)
        #pragma unroll
        for (int ks = 0; ks < 2; ks++) {
            const int row = wid*32 + mt*16 + gid;
            const int k0  = ks*16 + 2*tig;
            qh[mt][ks][0] = *(const u32*)&smb[SQH + row*QSTR + k0];
            qh[mt][ks][1] = *(const u32*)&smb[SQH + (row+8)*QSTR + k0];
            qh[mt][ks][2] = *(const u32*)&smb[SQH + row*QSTR + k0 + 8];
            qh[mt][ks][3] = *(const u32*)&smb[SQH + (row+8)*QSTR + k0 + 8];
            ql[mt][ks][0] = *(const u32*)&smb[SQL + row*QSTR + k0];
            ql[mt][ks][1] = *(const u32*)&smb[SQL + (row+8)*QSTR + k0];
            ql[mt][ks][2] = *(const u32*)&smb[SQL + row*QSTR + k0 + 8];
            ql[mt][ks][3] = *(const u32*)&smb[SQL + (row+8)*QSTR + k0 + 8];
        }

    float acc[2][4][4];
    #pragma unroll
    for (int i = 0; i < 2; i++)
        #pragma unroll
        for (int j = 0; j < 4; j++)
            #pragma unroll
            for (int k = 0; k < 4; k++) acc[i][j][k] = 0.f;
    float lsum[4] = {0.f, 0.f, 0.f, 0.f};

    const float* rp = g_rpbT + (size_t)h*(NTOK*NTOK);

    #pragma unroll 1
    for (int kt = 0; kt < 16; kt++) {
        float rb[2][2][4];
        #pragma unroll
        for (int mt = 0; mt < 2; mt++)
            #pragma unroll
            for (int n8 = 0; n8 < 2; n8++) {
                const int col = kt*16 + n8*8 + 2*tig;
                const int row = wid*32 + mt*16 + gid;
                rb[mt][n8][0] = rp[col*NTOK + row];
                rb[mt][n8][1] = rp[(col+1)*NTOK + row];
                rb[mt][n8][2] = rp[col*NTOK + row + 8];
                rb[mt][n8][3] = rp[(col+1)*NTOK + row + 8];
            }

        u32 kbh[2][2][2], kbl[2][2][2];
        #pragma unroll
        for (int n8 = 0; n8 < 2; n8++)
            #pragma unroll
            for (int ks = 0; ks < 2; ks++) {
                const int key = kt*16 + n8*8 + gid;
                const int k0  = ks*16 + 2*tig;
                kbh[n8][ks][0] = *(const u32*)&smb[SKH + key*QSTR + k0];
                kbh[n8][ks][1] = *(const u32*)&smb[SKH + key*QSTR + k0 + 8];
                kbl[n8][ks][0] = *(const u32*)&smb[SKL + key*QSTR + k0];
                kbl[n8][ks][1] = *(const u32*)&smb[SKL + key*QSTR + k0 + 8];
            }

        float c[2][2][4];
        #pragma unroll
        for (int i = 0; i < 2; i++)
            #pragma unroll
            for (int j = 0; j < 2; j++)
                #pragma unroll
                for (int k = 0; k < 4; k++) c[i][j][k] = 0.f;
        #pragma unroll
        for (int mt = 0; mt < 2; mt++)
            #pragma unroll
            for (int n8 = 0; n8 < 2; n8++)
                #pragma unroll
                for (int ks = 0; ks < 2; ks++) {
                    mma16816(c[mt][n8], qh[mt][ks], kbh[n8][ks][0], kbh[n8][ks][1]);
                    mma16816(c[mt][n8], qh[mt][ks], kbl[n8][ks][0], kbl[n8][ks][1]);
                    mma16816(c[mt][n8], ql[mt][ks], kbh[n8][ks][0], kbh[n8][ks][1]);
                }

        #pragma unroll
        for (int mt = 0; mt < 2; mt++)
            #pragma unroll
            for (int n8 = 0; n8 < 2; n8++)
                #pragma unroll
                for (int e = 0; e < 4; e++) {
                    float pv = __expf(c[mt][n8][e] + rb[mt][n8][e] - M);
                    lsum[mt*2 + (e>>1)] += pv;
                    c[mt][n8][e] = pv;
                }

        u32 ah[2][4], al[2][4];
        #pragma unroll
        for (int mt = 0; mt < 2; mt++) {
            __nv_bfloat16 h0,l0,h1,l1;
            splitb(c[mt][0][0], h0, l0); splitb(c[mt][0][1], h1, l1);
            ah[mt][0] = packb(h0,h1); al[mt][0] = packb(l0,l1);
            splitb(c[mt][0][2], h0, l0); splitb(c[mt][0][3], h1, l1);
            ah[mt][1] = packb(h0,h1); al[mt][1] = packb(l0,l1);
            splitb(c[mt][1][0], h0, l0); splitb(c[mt][1][1], h1, l1);
            ah[mt][2] = packb(h0,h1); al[mt][2] = packb(l0,l1);
            splitb(c[mt][1][2], h0, l0); splitb(c[mt][1][3], h1, l1);
            ah[mt][3] = packb(h0,h1); al[mt][3] = packb(l0,l1);
        }

        #pragma unroll
        for (int n8d = 0; n8d < 4; n8d++) {
            const int dim = n8d*8 + gid;
            const int k0  = kt*16 + 2*tig;
            u32 vh0 = *(const u32*)&smb[SVH + dim*VSTR + k0];
            u32 vh1 = *(const u32*)&smb[SVH + dim*VSTR + k0 + 8];
            u32 vl0 = *(const u32*)&smb[SVL + dim*VSTR + k0];
            u32 vl1 = *(const u32*)&smb[SVL + dim*VSTR + k0 + 8];
            #pragma unroll
            for (int mt = 0; mt < 2; mt++) {
                mma16816(acc[mt][n8d], ah[mt], vh0, vh1);
                mma16816(acc[mt][n8d], ah[mt], vl0, vl1);
                mma16816(acc[mt][n8d], al[mt], vh0, vh1);
            }
        }
    }

    #pragma unroll
    for (int i = 0; i < 4; i++) {
        lsum[i] += __shfl_xor_sync(0xffffffffu, lsum[i], 1);
        lsum[i] += __shfl_xor_sync(0xffffffffu, lsum[i], 2);
        lsum[i] = 1.f / lsum[i];
    }

    #pragma unroll
    for (int mt = 0; mt < 2; mt++)
        #pragma unroll
        for (int n8d = 0; n8d < 4; n8d++) {
            const int row0 = wid*32 + mt*16 + gid;
            const int dim  = n8d*8 + 2*tig;
            const float i0 = lsum[mt*2], i1 = lsum[mt*2+1];
            float v0 = acc[mt][n8d][0]*i0, v1 = acc[mt][n8d][1]*i0;
            float v2 = acc[mt][n8d][2]*i1, v3 = acc[mt][n8d][3]*i1;
            size_t o0 = ((size_t)(b*NTOK + row0))*NC + h*DH + dim;
            size_t o1 = ((size_t)(b*NTOK + row0 + 8))*NC + h*DH + dim;
            __nv_bfloat16 b0 = __float2bfloat16(v0), b1 = __float2bfloat16(v1);
            __nv_bfloat16 b2 = __float2bfloat16(v2), b3 = __float2bfloat16(v3);
            *(__nv_bfloat162*)&g_aoh[o0] = __nv_bfloat162(b0, b1);
            *(__nv_bfloat162*)&g_aoh[o1] = __nv_bfloat162(b2, b3);
            *(__nv_bfloat162*)&g_aol[o0] = __nv_bfloat162(
                __float2bfloat16(v0 - __bfloat162float(b0)),
                __float2bfloat16(v1 - __bfloat162float(b1)));
            *(__nv_bfloat162*)&g_aol[o1] = __nv_bfloat162(
                __float2bfloat16(v2 - __bfloat162float(b2)),
                __float2bfloat16(v3 - __bfloat162float(b3)));
        }
}

// =========================== launcher ====================================
extern "C" void kernel_launch(void* const* d_in, const int* in_sizes, int n_in,
                              void* d_out, int out_size)
{
    const float* x      = (const float*)d_in[0];
    const float* qkv_w  = (const float*)d_in[1];
    const float* q_bias = (const float*)d_in[2];
    const float* v_bias = (const float*)d_in[3];
    const float* lscale = (const float*)d_in[4];
    const float* cpb_w1 = (const float*)d_in[5];
    const float* cpb_b1 = (const float*)d_in[6];
    const float* cpb_w2 = (const float*)d_in[7];
    const float* proj_w = (const float*)d_in[8];
    const float* proj_b = (const float*)d_in[9];
    const float* rtab   = (const float*)d_in[10];
    const int*   rpi    = (const int*)d_in[11];
    float* out = (float*)d_out;

    cudaFuncSetAttribute(attn_kernel, cudaFuncAttributeMaxDynamicSharedMemorySize, ATT_SMEM);

    {
        int n4 = MROWS*NC/4;
        split_kernel<<<(n4+255)/256, 256>>>(x, n4, 0);
        int w4 = 1152*NC/4;
        split_kernel<<<(w4+255)/256, 256>>>(qkv_w, w4, 1);
        int p4 = NC*NC/4;
        split_kernel<<<(p4+255)/256, 256>>>(proj_w, p4, 2);
    }

    cpb_kernel<<<961, 512>>>(rtab, cpb_w1, cpb_b1, cpb_w2);
    gather_kernel<<<NTOK, NTOK>>>(rpi);

    dim3 gq(1152/128, MROWS/128);
    qkv_hm_kernel<<<gq, 256, HM_SMEM>>>(q_bias, v_bias);

    attn_kernel<<<NWIN*NH, 256, ATT_SMEM>>>(lscale);

    dim3 gp(NC/128, MROWS/128);
    proj_hm_kernel<<<gp, 256, HM_SMEM>>>(proj_b, out);
}